// round 11
// baseline (speedup 1.0000x reference)
#include <cuda_runtime.h>
#include <cuda_bf16.h>
#include <math_constants.h>
#include <cstdint>

#define B_ 4
#define T_ 2048
#define TKV_ 512
#define D_ 1024
#define H_ 16
#define HD_ 64
#define HIDDEN_ 2736
#define EPS_ 1e-6f

// ---------------- fp32 scratch arena ----------------
static constexpr size_t SLOT = (size_t)B_ * T_ * D_;          // 8,388,608 floats
__device__ float g_scratch[7 * SLOT];

static constexpr int OFF_Q    = 0;                   // o-proj outs / tmp
static constexpr int OFF_V    = (int)(2 * SLOT);     // fp32 V (pre-transpose)
static constexpr int OFF_X1   = (int)(4 * SLOT);
static constexpr int OFF_X2   = (int)(6 * SLOT);
static constexpr int OFF_H1   = 0;                   // FFN overlays (Q,V dead)
static constexpr int OFF_H3   = (int)(1 * SLOT);     // fits: 8192*2736 = 22.4M < 3*SLOT? H1 needs 22.4M -> spans slots 0-2
static constexpr int OFF_H3B  = (int)(3 * SLOT);     // real H3 offset (22.4M at 3*SLOT .. fits in 7*SLOT? 3*SLOT+22.4M=47.6M < 58.7M ok)
static constexpr int OFF_FTMP = (int)(2 * SLOT);     // unused during FFN h-phase? -> use X1 slot region? keep distinct:
// H1: [0 .. 22.4M) spans slots 0-2.67 ; H3: [3*SLOT=25.2M .. 47.6M) ; X2 at 6*SLOT=50.3M safe.
// FTMP (w2 out, 8.4M): place at 0 (H1 dead after silu? NO - silu reads H1 then w2 reads split; H1 dead after silu) -> FTMP=0 ok... but launch ordering: silu consumes H1/H3 before w2 gemm writes FTMP. Use FTMP=0.
static constexpr int OFF_FT2  = 0;

// ---------------- bf16 arena ----------------
static constexpr size_t ACT   = (size_t)8192 * 2752;          // 22,544,384
static constexpr size_t WSLOT = (size_t)1024 * 2752;          // 2,818,048
static constexpr int OFF_AHI  = 0;
static constexpr int OFF_ALO  = (int)ACT;
static constexpr int OFF_WB   = (int)(2 * ACT);               // 11 weights x (hi,lo)
static constexpr int OFF_ATTB = (int)(2 * ACT + 22 * WSLOT);  // 107,085,824
static constexpr int ATT_QHI  = OFF_ATTB;
static constexpr int ATT_QLO  = OFF_ATTB + (int)(1 * SLOT);
static constexpr int ATT_KHI  = OFF_ATTB + (int)(2 * SLOT);
static constexpr int ATT_KLO  = OFF_ATTB + (int)(3 * SLOT);
static constexpr int ATT_VTHI = OFF_ATTB + (int)(4 * SLOT);
static constexpr int ATT_VTLO = OFF_ATTB + (int)(5 * SLOT);
__device__ __nv_bfloat16 g_bf[2 * ACT + 22 * WSLOT + 6 * SLOT];

static __host__ __device__ constexpr int WHI(int i) { return OFF_WB + (int)(2 * i * WSLOT); }
static __host__ __device__ constexpr int WLO(int i) { return OFF_WB + (int)((2 * i + 1) * WSLOT); }

// ================= asm helpers =================
__device__ __forceinline__ uint32_t smem_to_u32(const void* p) {
    uint32_t a;
    asm("{ .reg .u64 tmp; cvta.to.shared.u64 tmp, %1; cvt.u32.u64 %0, tmp; }"
        : "=r"(a) : "l"(p));
    return a;
}
__device__ __forceinline__ void lds32(uint32_t& x, uint32_t addr) {
    asm volatile("ld.shared.b32 %0, [%1];" : "=r"(x) : "r"(addr));
}
__device__ __forceinline__ void ldmx4(uint32_t& r0, uint32_t& r1, uint32_t& r2, uint32_t& r3,
                                      uint32_t addr) {
    asm volatile("ldmatrix.sync.aligned.m8n8.x4.shared.b16 {%0,%1,%2,%3}, [%4];"
                 : "=r"(r0), "=r"(r1), "=r"(r2), "=r"(r3) : "r"(addr));
}
__device__ __forceinline__ void mma16816(float* c, const uint32_t* a, const uint32_t* b) {
    asm volatile(
        "mma.sync.aligned.m16n8k16.row.col.f32.bf16.bf16.f32 "
        "{%0,%1,%2,%3}, {%4,%5,%6,%7}, {%8,%9}, {%0,%1,%2,%3};"
        : "+f"(c[0]), "+f"(c[1]), "+f"(c[2]), "+f"(c[3])
        : "r"(a[0]), "r"(a[1]), "r"(a[2]), "r"(a[3]), "r"(b[0]), "r"(b[1]));
}
__device__ __forceinline__ void cp_async16(uint32_t dst, const void* src, int sz) {
    asm volatile("cp.async.cg.shared.global [%0], [%1], 16, %2;"
                 :: "r"(dst), "l"(src), "r"(sz));
}
#define CP_COMMIT() asm volatile("cp.async.commit_group;" ::: "memory")
#define CP_WAIT(n)  asm volatile("cp.async.wait_group %0;" :: "n"(n) : "memory")

__device__ __forceinline__ void split_bf16(float v, __nv_bfloat16& h, __nv_bfloat16& l) {
    h = __float2bfloat16(v);
    l = __float2bfloat16(v - __bfloat162float(h));
}
__device__ __forceinline__ uint32_t pack_hi(float a, float b) {
    __nv_bfloat16 h0, l0, h1, l1;
    split_bf16(a, h0, l0); split_bf16(b, h1, l1);
    __nv_bfloat162 H = {h0, h1};
    return *(const uint32_t*)&H;
}
__device__ __forceinline__ void pack_split2(float a, float b, uint32_t& hi, uint32_t& lo) {
    __nv_bfloat16 h0, l0, h1, l1;
    split_bf16(a, h0, l0); split_bf16(b, h1, l1);
    __nv_bfloat162 H = {h0, h1}, L = {l0, l1};
    hi = *(const uint32_t*)&H; lo = *(const uint32_t*)&L;
}

// ================= conversion kernels =================
// fp32 [M,K] (external) -> bf16 hi/lo [M,Kp]
__global__ void conv_act(const float* __restrict__ src, int M, int K, int Kp) {
    const int idx = blockIdx.x * blockDim.x + threadIdx.x;
    const int kq = Kp >> 2;
    if (idx >= M * kq) return;
    const int row = idx / kq;
    const int c4 = (idx - row * kq) * 4;
    __nv_bfloat16 h[4], l[4];
#pragma unroll
    for (int j = 0; j < 4; j++) {
        const int c = c4 + j;
        const float v = (c < K) ? src[(size_t)row * K + c] : 0.f;
        split_bf16(v, h[j], l[j]);
    }
    const size_t o = (size_t)row * Kp + c4;
    *(uint2*)&g_bf[OFF_AHI + o] = *(const uint2*)h;
    *(uint2*)&g_bf[OFF_ALO + o] = *(const uint2*)l;
}

// weight fp32 [K,N] -> transposed bf16 hi/lo [N,Kp] at whi/wlo
__global__ void conv_wt_t(const float* __restrict__ W, int K, int N, int Kp,
                          int whi, int wlo) {
    __shared__ float t[32][33];
    const int k0 = blockIdx.x * 32, n0 = blockIdx.y * 32;
    const int tx = threadIdx.x, ty = threadIdx.y;
#pragma unroll
    for (int i = 0; i < 4; i++) {
        const int k = k0 + ty + i * 8, n = n0 + tx;
        t[ty + i * 8][tx] = (k < K && n < N) ? W[(size_t)k * N + n] : 0.f;
    }
    __syncthreads();
#pragma unroll
    for (int i = 0; i < 4; i++) {
        const int n = n0 + ty + i * 8, k = k0 + tx;
        if (n < N) {
            __nv_bfloat16 h, l;
            split_bf16(t[tx][ty + i * 8], h, l);
            g_bf[whi + (size_t)n * Kp + k] = h;
            g_bf[wlo + (size_t)n * Kp + k] = l;
        }
    }
}

// V fp32 (b,t,h,d) -> transposed bf16 hi/lo [b][h][d][Tk]
__global__ void conv_v_t(int voff, int Tk) {
    __shared__ float t[32][33];
    const int t0 = blockIdx.x * 32, d0 = blockIdx.y * 32;
    const int b = blockIdx.z >> 4, h = blockIdx.z & 15;
    const int tx = threadIdx.x, ty = threadIdx.y;
    const float* __restrict__ V = g_scratch + voff;
#pragma unroll
    for (int i = 0; i < 4; i++) {
        const int tt = t0 + ty + i * 8;
        t[ty + i * 8][tx] = V[((size_t)(b * Tk + tt)) * D_ + h * HD_ + d0 + tx];
    }
    __syncthreads();
#pragma unroll
    for (int i = 0; i < 4; i++) {
        const int d = d0 + ty + i * 8;
        __nv_bfloat16 h16, l16;
        split_bf16(t[tx][ty + i * 8], h16, l16);
        const size_t o = ((size_t)((b * H_ + h) * HD_ + d)) * Tk + t0 + tx;
        g_bf[ATT_VTHI + o] = h16;
        g_bf[ATT_VTLO + o] = l16;
    }
}

// ================= HMMA bf16x3 GEMM with fused epilogue =================
static constexpr int OPB  = 128 * 40 * 2;
static constexpr int STAGEB = 4 * OPB;
static constexpr int GSMEM = 2 * STAGEB;

__device__ __forceinline__ void cp_stage(const __nv_bfloat16* __restrict__ src, int kp,
                                         int kb, int rbase, int rlimit,
                                         uint32_t dstbase, int tid) {
#pragma unroll
    for (int rep = 0; rep < 2; rep++) {
        const int u = tid + rep * 256;
        const int r = u >> 2, seg = u & 3;
        const int gr = rbase + r;
        const int cl = (gr < rlimit) ? gr : (rlimit - 1);
        const void* gsrc = src + (size_t)cl * kp + kb + seg * 8;
        cp_async16(dstbase + r * 80 + seg * 16, gsrc, (gr < rlimit) ? 16 : 0);
    }
}

// epilogue modes: splitHi>=0 -> write bf16 hi/lo [M,1024]; ropeF!=null -> apply rope first.
__global__ __launch_bounds__(256, 1) void gemm_hmma(int coff, int splitHi, int splitLo,
                                                    const float* __restrict__ ropeF,
                                                    int M, int N, int kp, int nchunk,
                                                    int bhi, int blo) {
    extern __shared__ char smem[];
    const uint32_t sb = smem_to_u32(smem);
    const int tid = threadIdx.x;
    const int wid = tid >> 5, lane = tid & 31;
    const int warpM = wid >> 2, warpN = wid & 3;
    const int lr = lane >> 2, lc = (lane & 3) * 2;
    const int rowBase = blockIdx.y * 128, colBase = blockIdx.x * 128;

    const __nv_bfloat16* Ahi = g_bf + OFF_AHI;
    const __nv_bfloat16* Alo = g_bf + OFF_ALO;
    const __nv_bfloat16* Bhi = g_bf + bhi;
    const __nv_bfloat16* Blo = g_bf + blo;

    // ldmatrix per-lane address offsets (within operand tile, excluding kk/base)
    const int j = lane >> 3, r = lane & 7;
    const uint32_t aLM = (uint32_t)((warpM * 64 + (j & 1) * 8 + r) * 80 + (j >> 1) * 16);
    const uint32_t bLM = (uint32_t)((warpN * 32 + (j >> 1) * 8 + r) * 80 + (j & 1) * 16);

    float C[4][4][4];
#pragma unroll
    for (int mt = 0; mt < 4; mt++)
#pragma unroll
        for (int nt = 0; nt < 4; nt++)
#pragma unroll
            for (int jj = 0; jj < 4; jj++) C[mt][nt][jj] = 0.f;

    cp_stage(Ahi, kp, 0, rowBase, M, sb + 0 * OPB, tid);
    cp_stage(Alo, kp, 0, rowBase, M, sb + 1 * OPB, tid);
    cp_stage(Bhi, kp, 0, colBase, N, sb + 2 * OPB, tid);
    cp_stage(Blo, kp, 0, colBase, N, sb + 3 * OPB, tid);
    CP_COMMIT();

    for (int c = 0; c < nchunk; c++) {
        if (c + 1 < nchunk) {
            const uint32_t nb = sb + ((c + 1) & 1) * STAGEB;
            const int kb = (c + 1) * 32;
            cp_stage(Ahi, kp, kb, rowBase, M, nb + 0 * OPB, tid);
            cp_stage(Alo, kp, kb, rowBase, M, nb + 1 * OPB, tid);
            cp_stage(Bhi, kp, kb, colBase, N, nb + 2 * OPB, tid);
            cp_stage(Blo, kp, kb, colBase, N, nb + 3 * OPB, tid);
            CP_COMMIT();
            CP_WAIT(1);
        } else {
            CP_WAIT(0);
        }
        __syncthreads();

        const uint32_t buf = sb + (c & 1) * STAGEB;
        const uint32_t aHiB = buf, aLoB = buf + OPB, bHiB = buf + 2 * OPB, bLoB = buf + 3 * OPB;

#pragma unroll
        for (int ks = 0; ks < 2; ks++) {
            const uint32_t kkb = (uint32_t)(ks * 32);   // kk*2 bytes
            uint32_t ahi[4][4], alo[4][4], bh[4][2], bl[4][2];
#pragma unroll
            for (int mt = 0; mt < 4; mt++) {
                const uint32_t ao = aLM + (uint32_t)(mt * 16 * 80) + kkb;
                ldmx4(ahi[mt][0], ahi[mt][1], ahi[mt][2], ahi[mt][3], aHiB + ao);
                ldmx4(alo[mt][0], alo[mt][1], alo[mt][2], alo[mt][3], aLoB + ao);
            }
#pragma unroll
            for (int p = 0; p < 2; p++) {
                const uint32_t bo = bLM + (uint32_t)(p * 16 * 80) + kkb;
                ldmx4(bh[2 * p][0], bh[2 * p][1], bh[2 * p + 1][0], bh[2 * p + 1][1], bHiB + bo);
                ldmx4(bl[2 * p][0], bl[2 * p][1], bl[2 * p + 1][0], bl[2 * p + 1][1], bLoB + bo);
            }
#pragma unroll
            for (int mt = 0; mt < 4; mt++)
#pragma unroll
                for (int nt = 0; nt < 4; nt++) {
                    mma16816(C[mt][nt], ahi[mt], bh[nt]);
                    mma16816(C[mt][nt], ahi[mt], bl[nt]);
                    mma16816(C[mt][nt], alo[mt], bh[nt]);
                }
        }
        __syncthreads();
    }

    if (splitHi >= 0) {
        // N == 1024 path: optional rope, then hi/lo split write
        __nv_bfloat16* __restrict__ GH = g_bf + splitHi;
        __nv_bfloat16* __restrict__ GL = g_bf + splitLo;
#pragma unroll
        for (int mt = 0; mt < 4; mt++) {
            const int row0 = rowBase + warpM * 64 + mt * 16 + lr;
#pragma unroll
            for (int nt = 0; nt < 4; nt++) {
                const int col = colBase + warpN * 32 + nt * 8 + lc;
                float v0 = C[mt][nt][0], v1 = C[mt][nt][1];
                float v2 = C[mt][nt][2], v3 = C[mt][nt][3];
                if (ropeF) {
                    const int i = (col & 63) >> 1;
                    const int t0 = row0 & (T_ - 1), t1 = (row0 + 8) & (T_ - 1);
                    const float c0 = ropeF[(t0 * 32 + i) * 2], s0 = ropeF[(t0 * 32 + i) * 2 + 1];
                    const float c1 = ropeF[(t1 * 32 + i) * 2], s1 = ropeF[(t1 * 32 + i) * 2 + 1];
                    const float a0 = v0 * c0 - v1 * s0, b0 = v0 * s0 + v1 * c0;
                    const float a1 = v2 * c1 - v3 * s1, b1 = v2 * s1 + v3 * c1;
                    v0 = a0; v1 = b0; v2 = a1; v3 = b1;
                }
                uint32_t hi, lo;
                pack_split2(v0, v1, hi, lo);
                *(uint32_t*)&GH[(size_t)row0 * 1024 + col] = hi;
                *(uint32_t*)&GL[(size_t)row0 * 1024 + col] = lo;
                pack_split2(v2, v3, hi, lo);
                *(uint32_t*)&GH[(size_t)(row0 + 8) * 1024 + col] = hi;
                *(uint32_t*)&GL[(size_t)(row0 + 8) * 1024 + col] = lo;
            }
        }
    } else {
        float* __restrict__ Co = g_scratch + coff;
#pragma unroll
        for (int mt = 0; mt < 4; mt++) {
            const int row0 = rowBase + warpM * 64 + mt * 16 + lr;
#pragma unroll
            for (int nt = 0; nt < 4; nt++) {
                const int col = colBase + warpN * 32 + nt * 8 + lc;
                if (col < N) {
                    *(float2*)(Co + (size_t)row0 * N + col) = make_float2(C[mt][nt][0], C[mt][nt][1]);
                    *(float2*)(Co + (size_t)(row0 + 8) * N + col) = make_float2(C[mt][nt][2], C[mt][nt][3]);
                }
            }
        }
    }
}

// ================= tensor-core flash attention (bf16x3) =================
static constexpr int FROW = 144;
static constexpr int F_QOP = 128 * FROW;
static constexpr int F_KOP = 64 * FROW;
static constexpr int F_STAGE = 4 * F_KOP;
static constexpr int FSMEM = 2 * F_QOP + 2 * F_STAGE;

template <bool CAUSAL>
__global__ __launch_bounds__(256) void flash_mma(int Tq, int Tk) {
    extern __shared__ char smem[];
    const uint32_t sb = smem_to_u32(smem);
    const uint32_t qHiB = sb, qLoB = sb + F_QOP;
    const uint32_t stg0 = sb + 2 * F_QOP;

    const int tid = threadIdx.x;
    const int wid = tid >> 5, lane = tid & 31;
    const int g = lane >> 2, t4 = lane & 3;
    const int q0 = blockIdx.x * 128;
    const int h = blockIdx.y, b = blockIdx.z;

    const __nv_bfloat16* Qhi = g_bf + ATT_QHI;
    const __nv_bfloat16* Qlo = g_bf + ATT_QLO;
    const __nv_bfloat16* Khi = g_bf + ATT_KHI;
    const __nv_bfloat16* Klo = g_bf + ATT_KLO;
    const __nv_bfloat16* Vthi = g_bf + ATT_VTHI;
    const __nv_bfloat16* Vtlo = g_bf + ATT_VTLO;

#pragma unroll
    for (int rep = 0; rep < 8; rep++) {
        const int u = tid + rep * 256;
        const int op = u >> 10;
        const int r = (u >> 3) & 127, seg = u & 7;
        const __nv_bfloat16* src = (op ? Qlo : Qhi) +
            ((size_t)(b * Tq + q0 + r)) * D_ + h * HD_ + seg * 8;
        cp_async16((op ? qLoB : qHiB) + r * FROW + seg * 16, src, 16);
    }
    {
#pragma unroll
        for (int rep = 0; rep < 8; rep++) {
            const int u = tid + rep * 256;
            const int op = u >> 9;
            const int r = (u >> 3) & 63, seg = u & 7;
            const __nv_bfloat16* src;
            if (op < 2)
                src = (op ? Klo : Khi) + ((size_t)(b * Tk + r)) * D_ + h * HD_ + seg * 8;
            else
                src = (op == 2 ? Vthi : Vtlo) +
                      ((size_t)((b * H_ + h) * HD_ + r)) * Tk + seg * 8;
            cp_async16(stg0 + op * F_KOP + r * FROW + seg * 16, src, 16);
        }
    }
    CP_COMMIT();

    float o[8][4];
#pragma unroll
    for (int nd = 0; nd < 8; nd++)
#pragma unroll
        for (int jj = 0; jj < 4; jj++) o[nd][jj] = 0.f;
    float m0 = -CUDART_INF_F, m1 = -CUDART_INF_F, l0 = 0.f, l1 = 0.f;
    uint32_t aqh[4][4], aql[4][4];

    const int kend = CAUSAL ? (q0 + 128) : Tk;
    const int niter = kend / 64;

    for (int c = 0; c < niter; c++) {
        const int k0 = c * 64;
        if (c + 1 < niter) {
            const int kn = k0 + 64;
            const uint32_t nstg = stg0 + ((c + 1) & 1) * F_STAGE;
#pragma unroll
            for (int rep = 0; rep < 8; rep++) {
                const int u = tid + rep * 256;
                const int op = u >> 9;
                const int r = (u >> 3) & 63, seg = u & 7;
                const __nv_bfloat16* src;
                if (op < 2)
                    src = (op ? Klo : Khi) + ((size_t)(b * Tk + kn + r)) * D_ + h * HD_ + seg * 8;
                else
                    src = (op == 2 ? Vthi : Vtlo) +
                          ((size_t)((b * H_ + h) * HD_ + r)) * Tk + kn + seg * 8;
                cp_async16(nstg + op * F_KOP + r * FROW + seg * 16, src, 16);
            }
            CP_COMMIT();
            CP_WAIT(1);
        } else {
            CP_WAIT(0);
        }
        __syncthreads();

        if (c == 0) {
#pragma unroll
            for (int kt = 0; kt < 4; kt++) {
                const uint32_t off = (uint32_t)((16 * wid + g) * FROW + (kt * 16 + 2 * t4) * 2);
                lds32(aqh[kt][0], qHiB + off);
                lds32(aqh[kt][1], qHiB + off + 8 * FROW);
                lds32(aqh[kt][2], qHiB + off + 16);
                lds32(aqh[kt][3], qHiB + off + 8 * FROW + 16);
                lds32(aql[kt][0], qLoB + off);
                lds32(aql[kt][1], qLoB + off + 8 * FROW);
                lds32(aql[kt][2], qLoB + off + 16);
                lds32(aql[kt][3], qLoB + off + 8 * FROW + 16);
            }
        }

        const uint32_t buf = stg0 + (c & 1) * F_STAGE;
        const uint32_t kHiB = buf, kLoB = buf + F_KOP;
        const uint32_t vHiB = buf + 2 * F_KOP, vLoB = buf + 3 * F_KOP;

        float s[8][4];
#pragma unroll
        for (int nt = 0; nt < 8; nt++) {
#pragma unroll
            for (int jj = 0; jj < 4; jj++) s[nt][jj] = 0.f;
#pragma unroll
            for (int kt = 0; kt < 4; kt++) {
                const uint32_t off = (uint32_t)((nt * 8 + g) * FROW + (kt * 16 + 2 * t4) * 2);
                uint32_t bh[2], bl[2];
                lds32(bh[0], kHiB + off); lds32(bh[1], kHiB + off + 16);
                lds32(bl[0], kLoB + off); lds32(bl[1], kLoB + off + 16);
                mma16816(s[nt], aqh[kt], bh);
                mma16816(s[nt], aqh[kt], bl);
                mma16816(s[nt], aql[kt], bh);
            }
        }

        const int row0 = q0 + 16 * wid + g, row1 = row0 + 8;
        const bool domask = CAUSAL && (k0 + 63 > q0);
#pragma unroll
        for (int nt = 0; nt < 8; nt++) {
            const int col = k0 + nt * 8 + 2 * t4;
#pragma unroll
            for (int jj = 0; jj < 4; jj++) s[nt][jj] *= 0.125f;
            if (domask) {
                if (col > row0)     s[nt][0] = -1e30f;
                if (col + 1 > row0) s[nt][1] = -1e30f;
                if (col > row1)     s[nt][2] = -1e30f;
                if (col + 1 > row1) s[nt][3] = -1e30f;
            }
        }

        float mx0 = -CUDART_INF_F, mx1 = -CUDART_INF_F;
#pragma unroll
        for (int nt = 0; nt < 8; nt++) {
            mx0 = fmaxf(mx0, fmaxf(s[nt][0], s[nt][1]));
            mx1 = fmaxf(mx1, fmaxf(s[nt][2], s[nt][3]));
        }
        mx0 = fmaxf(mx0, __shfl_xor_sync(0xffffffffu, mx0, 1));
        mx0 = fmaxf(mx0, __shfl_xor_sync(0xffffffffu, mx0, 2));
        mx1 = fmaxf(mx1, __shfl_xor_sync(0xffffffffu, mx1, 1));
        mx1 = fmaxf(mx1, __shfl_xor_sync(0xffffffffu, mx1, 2));
        const float mn0 = fmaxf(m0, mx0), mn1 = fmaxf(m1, mx1);
        const float sc0 = __expf(m0 - mn0), sc1 = __expf(m1 - mn1);

        uint32_t ph[8][2], pl[8][2];
        float sum0 = 0.f, sum1 = 0.f;
#pragma unroll
        for (int nt = 0; nt < 8; nt++) {
            const float p0 = __expf(s[nt][0] - mn0);
            const float p1 = __expf(s[nt][1] - mn0);
            const float p2 = __expf(s[nt][2] - mn1);
            const float p3 = __expf(s[nt][3] - mn1);
            sum0 += p0 + p1; sum1 += p2 + p3;
            pack_split2(p0, p1, ph[nt][0], pl[nt][0]);
            pack_split2(p2, p3, ph[nt][1], pl[nt][1]);
        }
        sum0 += __shfl_xor_sync(0xffffffffu, sum0, 1);
        sum0 += __shfl_xor_sync(0xffffffffu, sum0, 2);
        sum1 += __shfl_xor_sync(0xffffffffu, sum1, 1);
        sum1 += __shfl_xor_sync(0xffffffffu, sum1, 2);
        l0 = l0 * sc0 + sum0; l1 = l1 * sc1 + sum1;
        m0 = mn0; m1 = mn1;

#pragma unroll
        for (int nd = 0; nd < 8; nd++) {
            o[nd][0] *= sc0; o[nd][1] *= sc0;
            o[nd][2] *= sc1; o[nd][3] *= sc1;
        }

#pragma unroll
        for (int jj = 0; jj < 4; jj++) {
            const uint32_t ah[4] = {ph[2 * jj][0], ph[2 * jj][1], ph[2 * jj + 1][0], ph[2 * jj + 1][1]};
            const uint32_t al[4] = {pl[2 * jj][0], pl[2 * jj][1], pl[2 * jj + 1][0], pl[2 * jj + 1][1]};
#pragma unroll
            for (int nd = 0; nd < 8; nd++) {
                const uint32_t off = (uint32_t)((nd * 8 + g) * FROW + (jj * 16 + 2 * t4) * 2);
                uint32_t bh[2], bl[2];
                lds32(bh[0], vHiB + off); lds32(bh[1], vHiB + off + 16);
                lds32(bl[0], vLoB + off); lds32(bl[1], vLoB + off + 16);
                mma16816(o[nd], ah, bh);
                mma16816(o[nd], ah, bl);
                mma16816(o[nd], al, bh);
            }
        }
        __syncthreads();
    }

    // epilogue: split-write directly into GEMM act slots [row, 1024]
    const float inv0 = 1.f / l0, inv1 = 1.f / l1;
    __nv_bfloat16* __restrict__ GH = g_bf + OFF_AHI;
    __nv_bfloat16* __restrict__ GL = g_bf + OFF_ALO;
    const int row0 = q0 + 16 * wid + g;
#pragma unroll
    for (int nd = 0; nd < 8; nd++) {
        const int col = h * HD_ + nd * 8 + 2 * t4;
        uint32_t hi, lo;
        pack_split2(o[nd][0] * inv0, o[nd][1] * inv0, hi, lo);
        *(uint32_t*)&GH[(size_t)(b * Tq + row0) * 1024 + col] = hi;
        *(uint32_t*)&GL[(size_t)(b * Tq + row0) * 1024 + col] = lo;
        pack_split2(o[nd][2] * inv1, o[nd][3] * inv1, hi, lo);
        *(uint32_t*)&GH[(size_t)(b * Tq + row0 + 8) * 1024 + col] = hi;
        *(uint32_t*)&GL[(size_t)(b * Tq + row0 + 8) * 1024 + col] = lo;
    }
}

// ================= residual + RMSNorm (+ optional split write) =================
__global__ __launch_bounds__(256) void residual_rmsnorm(const float* __restrict__ xext, int xoff,
                                                        int doff,
                                                        const float* __restrict__ g,
                                                        float* __restrict__ outext, int outoff,
                                                        int splitHi, int splitLo) {
    const float* __restrict__ xin = xext ? xext : (const float*)(g_scratch + xoff);
    const float* __restrict__ d = g_scratch + doff;
    float* __restrict__ out = outext ? outext : (g_scratch + outoff);

    __shared__ float red[8];
    const int row = blockIdx.x, tid = threadIdx.x;
    const size_t base = (size_t)row * D_;
    float4 a = *(const float4*)(xin + base + tid * 4);
    float4 bb = *(const float4*)(d + base + tid * 4);
    const float v0 = a.x + bb.x, v1 = a.y + bb.y, v2 = a.z + bb.z, v3 = a.w + bb.w;
    float ss = v0 * v0 + v1 * v1 + v2 * v2 + v3 * v3;
#pragma unroll
    for (int o = 16; o > 0; o >>= 1) ss += __shfl_xor_sync(0xffffffffu, ss, o);
    if ((tid & 31) == 0) red[tid >> 5] = ss;
    __syncthreads();
    if (tid < 8) {
        float t = red[tid];
#pragma unroll
        for (int o = 4; o > 0; o >>= 1) t += __shfl_xor_sync(0xffu, t, o);
        if (tid == 0) red[0] = t;
    }
    __syncthreads();
    const float r = rsqrtf(red[0] * (1.f / (float)D_) + EPS_);
    float4 gg = *(const float4*)(g + tid * 4);
    float4 o4 = make_float4(v0 * r * gg.x, v1 * r * gg.y, v2 * r * gg.z, v3 * r * gg.w);
    *(float4*)(out + base + tid * 4) = o4;
    if (splitHi >= 0) {
        uint32_t h0, l0, h1, l1;
        pack_split2(o4.x, o4.y, h0, l0);
        pack_split2(o4.z, o4.w, h1, l1);
        uint2 H = make_uint2(h0, h1), L = make_uint2(l0, l1);
        *(uint2*)&g_bf[splitHi + base + tid * 4] = H;
        *(uint2*)&g_bf[splitLo + base + tid * 4] = L;
    }
}

// ================= SwiGLU gate -> padded split [M,2752] =================
__global__ void silu_split(int h1off, int h3off, int M) {
    const int idx = blockIdx.x * blockDim.x + threadIdx.x;   // M * 688
    const int kq = 2752 >> 2;
    if (idx >= M * kq) return;
    const int row = idx / kq;
    const int c4 = (idx - row * kq) * 4;
    uint32_t h0, l0, h1, l1;
    if (c4 < HIDDEN_) {
        const float4 a = *(const float4*)(g_scratch + h1off + (size_t)row * HIDDEN_ + c4);
        const float4 b = *(const float4*)(g_scratch + h3off + (size_t)row * HIDDEN_ + c4);
        const float y0 = a.x / (1.f + __expf(-a.x)) * b.x;
        const float y1 = a.y / (1.f + __expf(-a.y)) * b.y;
        const float y2 = a.z / (1.f + __expf(-a.z)) * b.z;
        const float y3 = a.w / (1.f + __expf(-a.w)) * b.w;
        pack_split2(y0, y1, h0, l0);
        pack_split2(y2, y3, h1, l1);
    } else {
        h0 = l0 = h1 = l1 = 0u;
    }
    const size_t o = (size_t)row * 2752 + c4;
    *(uint2*)&g_bf[OFF_AHI + o] = make_uint2(h0, h1);
    *(uint2*)&g_bf[OFF_ALO + o] = make_uint2(l0, l1);
}

// ================= launcher =================
static void launch_gemm(int coff, int splitHi, int splitLo, const float* ropeF,
                        int M, int N, int kp, int whi, int wlo) {
    gemm_hmma<<<dim3((N + 127) / 128, M / 128), 256, GSMEM>>>(
        coff, splitHi, splitLo, ropeF, M, N, kp, kp / 32, whi, wlo);
}
static void launch_conv_wt(const float* W, int K, int N, int Kp, int wi) {
    conv_wt_t<<<dim3(Kp / 32, (N + 31) / 32), dim3(32, 8)>>>(W, K, N, Kp, WHI(wi), WLO(wi));
}

extern "C" void kernel_launch(void* const* d_in, const int* in_sizes, int n_in,
                              void* d_out, int out_size) {
    const float* x     = (const float*)d_in[0];
    const float* mem   = (const float*)d_in[1];
    const float* freqs = (const float*)d_in[2];
    const float* sa_wq = (const float*)d_in[4];
    const float* sa_wk = (const float*)d_in[5];
    const float* sa_wv = (const float*)d_in[6];
    const float* sa_wo = (const float*)d_in[7];
    const float* ca_wq = (const float*)d_in[8];
    const float* ca_wk = (const float*)d_in[9];
    const float* ca_wv = (const float*)d_in[10];
    const float* ca_wo = (const float*)d_in[11];
    const float* w1    = (const float*)d_in[12];
    const float* w3    = (const float*)d_in[13];
    const float* w2    = (const float*)d_in[14];
    const float* gsa   = (const float*)d_in[15];
    const float* gca   = (const float*)d_in[16];
    const float* gffn  = (const float*)d_in[17];
    float* out = (float*)d_out;

    cudaFuncSetAttribute((const void*)gemm_hmma,
                         cudaFuncAttributeMaxDynamicSharedMemorySize, GSMEM);
    cudaFuncSetAttribute((const void*)flash_mma<true>,
                         cudaFuncAttributeMaxDynamicSharedMemorySize, FSMEM);
    cudaFuncSetAttribute((const void*)flash_mma<false>,
                         cudaFuncAttributeMaxDynamicSharedMemorySize, FSMEM);

    const int MT = B_ * T_;     // 8192
    const int MKV = B_ * TKV_;  // 2048
    const dim3 gflash(T_ / 128, H_, B_);

    // ---- self-attention ----
    conv_act<<<(MT * 256 + 255) / 256, 256>>>(x, MT, D_, D_);                  // #0
    launch_conv_wt(sa_wq, D_, D_, D_, 0);                                      // #1
    launch_conv_wt(sa_wk, D_, D_, D_, 1);                                      // #2
    launch_conv_wt(sa_wv, D_, D_, D_, 2);                                      // #3
    launch_conv_wt(sa_wo, D_, D_, D_, 3);                                      // #4
    launch_gemm(0, ATT_QHI, ATT_QLO, freqs, MT, D_, D_, WHI(0), WLO(0));       // #5 <- profiled
    launch_gemm(0, ATT_KHI, ATT_KLO, freqs, MT, D_, D_, WHI(1), WLO(1));
    launch_gemm(OFF_V, -1, -1, nullptr, MT, D_, D_, WHI(2), WLO(2));
    conv_v_t<<<dim3(T_ / 32, 2, B_ * H_), dim3(32, 8)>>>(OFF_V, T_);
    flash_mma<true><<<gflash, 256, FSMEM>>>(T_, T_);
    launch_gemm(OFF_Q, -1, -1, nullptr, MT, D_, D_, WHI(3), WLO(3));
    residual_rmsnorm<<<MT, 256>>>(x, 0, OFF_Q, gsa, nullptr, OFF_X1, OFF_AHI, OFF_ALO);

    // ---- cross-attention ----
    launch_conv_wt(ca_wq, D_, D_, D_, 4);
    launch_conv_wt(ca_wk, D_, D_, D_, 5);
    launch_conv_wt(ca_wv, D_, D_, D_, 6);
    launch_conv_wt(ca_wo, D_, D_, D_, 7);
    launch_gemm(0, ATT_QHI, ATT_QLO, nullptr, MT, D_, D_, WHI(4), WLO(4));
    conv_act<<<(MKV * 256 + 255) / 256, 256>>>(mem, MKV, D_, D_);
    launch_gemm(0, ATT_KHI, ATT_KLO, nullptr, MKV, D_, D_, WHI(5), WLO(5));
    launch_gemm(OFF_V, -1, -1, nullptr, MKV, D_, D_, WHI(6), WLO(6));
    conv_v_t<<<dim3(TKV_ / 32, 2, B_ * H_), dim3(32, 8)>>>(OFF_V, TKV_);
    flash_mma<false><<<gflash, 256, FSMEM>>>(T_, TKV_);
    launch_gemm(OFF_Q, -1, -1, nullptr, MT, D_, D_, WHI(7), WLO(7));
    residual_rmsnorm<<<MT, 256>>>(nullptr, OFF_X1, OFF_Q, gca, nullptr, OFF_X2, OFF_AHI, OFF_ALO);

    // ---- FFN ----
    launch_conv_wt(w1, D_, HIDDEN_, D_, 8);
    launch_conv_wt(w3, D_, HIDDEN_, D_, 9);
    launch_conv_wt(w2, HIDDEN_, D_, 2752, 10);
    launch_gemm(OFF_H1, -1, -1, nullptr, MT, HIDDEN_, D_, WHI(8), WLO(8));
    launch_gemm(OFF_H3B, -1, -1, nullptr, MT, HIDDEN_, D_, WHI(9), WLO(9));
    silu_split<<<(MT * 688 + 255) / 256, 256>>>(OFF_H1, OFF_H3B, MT);
    launch_gemm(OFF_FT2, -1, -1, nullptr, MT, D_, 2752, WHI(10), WLO(10));
    residual_rmsnorm<<<MT, 256>>>(nullptr, OFF_X2, OFF_FT2, gffn, out, 0, -1, -1);
}

// round 12
// speedup vs baseline: 1.0019x; 1.0019x over previous
#include <cuda_runtime.h>
#include <cuda_bf16.h>
#include <math_constants.h>
#include <cstdint>

#define B_ 4
#define T_ 2048
#define TKV_ 512
#define D_ 1024
#define H_ 16
#define HD_ 64
#define HIDDEN_ 2736
#define EPS_ 1e-6f

// ---------------- fp32 scratch arena ----------------
static constexpr size_t SLOT = (size_t)B_ * T_ * D_;          // 8,388,608 floats
__device__ float g_scratch[7 * SLOT];

static constexpr int OFF_Q    = 0;                   // o-proj outs / tmp
static constexpr int OFF_V    = (int)(2 * SLOT);     // fp32 V (pre-transpose)
static constexpr int OFF_X1   = (int)(4 * SLOT);
static constexpr int OFF_X2   = (int)(6 * SLOT);
static constexpr int OFF_H1   = 0;                   // FFN overlays (Q,V dead)
static constexpr int OFF_H3   = (int)(1 * SLOT);     // fits: 8192*2736 = 22.4M < 3*SLOT? H1 needs 22.4M -> spans slots 0-2
static constexpr int OFF_H3B  = (int)(3 * SLOT);     // real H3 offset (22.4M at 3*SLOT .. fits in 7*SLOT? 3*SLOT+22.4M=47.6M < 58.7M ok)
static constexpr int OFF_FTMP = (int)(2 * SLOT);     // unused during FFN h-phase? -> use X1 slot region? keep distinct:
// H1: [0 .. 22.4M) spans slots 0-2.67 ; H3: [3*SLOT=25.2M .. 47.6M) ; X2 at 6*SLOT=50.3M safe.
// FTMP (w2 out, 8.4M): place at 0 (H1 dead after silu? NO - silu reads H1 then w2 reads split; H1 dead after silu) -> FTMP=0 ok... but launch ordering: silu consumes H1/H3 before w2 gemm writes FTMP. Use FTMP=0.
static constexpr int OFF_FT2  = 0;

// ---------------- bf16 arena ----------------
static constexpr size_t ACT   = (size_t)8192 * 2752;          // 22,544,384
static constexpr size_t WSLOT = (size_t)1024 * 2752;          // 2,818,048
static constexpr int OFF_AHI  = 0;
static constexpr int OFF_ALO  = (int)ACT;
static constexpr int OFF_WB   = (int)(2 * ACT);               // 11 weights x (hi,lo)
static constexpr int OFF_ATTB = (int)(2 * ACT + 22 * WSLOT);  // 107,085,824
static constexpr int ATT_QHI  = OFF_ATTB;
static constexpr int ATT_QLO  = OFF_ATTB + (int)(1 * SLOT);
static constexpr int ATT_KHI  = OFF_ATTB + (int)(2 * SLOT);
static constexpr int ATT_KLO  = OFF_ATTB + (int)(3 * SLOT);
static constexpr int ATT_VTHI = OFF_ATTB + (int)(4 * SLOT);
static constexpr int ATT_VTLO = OFF_ATTB + (int)(5 * SLOT);
__device__ __nv_bfloat16 g_bf[2 * ACT + 22 * WSLOT + 6 * SLOT];

static __host__ __device__ constexpr int WHI(int i) { return OFF_WB + (int)(2 * i * WSLOT); }
static __host__ __device__ constexpr int WLO(int i) { return OFF_WB + (int)((2 * i + 1) * WSLOT); }

// ================= asm helpers =================
__device__ __forceinline__ uint32_t smem_to_u32(const void* p) {
    uint32_t a;
    asm("{ .reg .u64 tmp; cvta.to.shared.u64 tmp, %1; cvt.u32.u64 %0, tmp; }"
        : "=r"(a) : "l"(p));
    return a;
}
__device__ __forceinline__ void lds32(uint32_t& x, uint32_t addr) {
    asm volatile("ld.shared.b32 %0, [%1];" : "=r"(x) : "r"(addr));
}
__device__ __forceinline__ void ldmx4(uint32_t& r0, uint32_t& r1, uint32_t& r2, uint32_t& r3,
                                      uint32_t addr) {
    asm volatile("ldmatrix.sync.aligned.m8n8.x4.shared.b16 {%0,%1,%2,%3}, [%4];"
                 : "=r"(r0), "=r"(r1), "=r"(r2), "=r"(r3) : "r"(addr));
}
__device__ __forceinline__ void mma16816(float* c, const uint32_t* a, const uint32_t* b) {
    asm volatile(
        "mma.sync.aligned.m16n8k16.row.col.f32.bf16.bf16.f32 "
        "{%0,%1,%2,%3}, {%4,%5,%6,%7}, {%8,%9}, {%0,%1,%2,%3};"
        : "+f"(c[0]), "+f"(c[1]), "+f"(c[2]), "+f"(c[3])
        : "r"(a[0]), "r"(a[1]), "r"(a[2]), "r"(a[3]), "r"(b[0]), "r"(b[1]));
}
__device__ __forceinline__ void cp_async16(uint32_t dst, const void* src, int sz) {
    asm volatile("cp.async.cg.shared.global [%0], [%1], 16, %2;"
                 :: "r"(dst), "l"(src), "r"(sz));
}
#define CP_COMMIT() asm volatile("cp.async.commit_group;" ::: "memory")
#define CP_WAIT(n)  asm volatile("cp.async.wait_group %0;" :: "n"(n) : "memory")

__device__ __forceinline__ void split_bf16(float v, __nv_bfloat16& h, __nv_bfloat16& l) {
    h = __float2bfloat16(v);
    l = __float2bfloat16(v - __bfloat162float(h));
}
__device__ __forceinline__ uint32_t pack_hi(float a, float b) {
    __nv_bfloat16 h0, l0, h1, l1;
    split_bf16(a, h0, l0); split_bf16(b, h1, l1);
    __nv_bfloat162 H = {h0, h1};
    return *(const uint32_t*)&H;
}
__device__ __forceinline__ void pack_split2(float a, float b, uint32_t& hi, uint32_t& lo) {
    __nv_bfloat16 h0, l0, h1, l1;
    split_bf16(a, h0, l0); split_bf16(b, h1, l1);
    __nv_bfloat162 H = {h0, h1}, L = {l0, l1};
    hi = *(const uint32_t*)&H; lo = *(const uint32_t*)&L;
}

// ================= conversion kernels =================
// fp32 [M,K] (external) -> bf16 hi/lo [M,Kp]
__global__ void conv_act(const float* __restrict__ src, int M, int K, int Kp) {
    const int idx = blockIdx.x * blockDim.x + threadIdx.x;
    const int kq = Kp >> 2;
    if (idx >= M * kq) return;
    const int row = idx / kq;
    const int c4 = (idx - row * kq) * 4;
    __nv_bfloat16 h[4], l[4];
#pragma unroll
    for (int j = 0; j < 4; j++) {
        const int c = c4 + j;
        const float v = (c < K) ? src[(size_t)row * K + c] : 0.f;
        split_bf16(v, h[j], l[j]);
    }
    const size_t o = (size_t)row * Kp + c4;
    *(uint2*)&g_bf[OFF_AHI + o] = *(const uint2*)h;
    *(uint2*)&g_bf[OFF_ALO + o] = *(const uint2*)l;
}

// weight fp32 [K,N] -> transposed bf16 hi/lo [N,Kp] at whi/wlo
__global__ void conv_wt_t(const float* __restrict__ W, int K, int N, int Kp,
                          int whi, int wlo) {
    __shared__ float t[32][33];
    const int k0 = blockIdx.x * 32, n0 = blockIdx.y * 32;
    const int tx = threadIdx.x, ty = threadIdx.y;
#pragma unroll
    for (int i = 0; i < 4; i++) {
        const int k = k0 + ty + i * 8, n = n0 + tx;
        t[ty + i * 8][tx] = (k < K && n < N) ? W[(size_t)k * N + n] : 0.f;
    }
    __syncthreads();
#pragma unroll
    for (int i = 0; i < 4; i++) {
        const int n = n0 + ty + i * 8, k = k0 + tx;
        if (n < N) {
            __nv_bfloat16 h, l;
            split_bf16(t[tx][ty + i * 8], h, l);
            g_bf[whi + (size_t)n * Kp + k] = h;
            g_bf[wlo + (size_t)n * Kp + k] = l;
        }
    }
}

// V fp32 (b,t,h,d) -> transposed bf16 hi/lo [b][h][d][Tk]
__global__ void conv_v_t(int voff, int Tk) {
    __shared__ float t[32][33];
    const int t0 = blockIdx.x * 32, d0 = blockIdx.y * 32;
    const int b = blockIdx.z >> 4, h = blockIdx.z & 15;
    const int tx = threadIdx.x, ty = threadIdx.y;
    const float* __restrict__ V = g_scratch + voff;
#pragma unroll
    for (int i = 0; i < 4; i++) {
        const int tt = t0 + ty + i * 8;
        t[ty + i * 8][tx] = V[((size_t)(b * Tk + tt)) * D_ + h * HD_ + d0 + tx];
    }
    __syncthreads();
#pragma unroll
    for (int i = 0; i < 4; i++) {
        const int d = d0 + ty + i * 8;
        __nv_bfloat16 h16, l16;
        split_bf16(t[tx][ty + i * 8], h16, l16);
        const size_t o = ((size_t)((b * H_ + h) * HD_ + d)) * Tk + t0 + tx;
        g_bf[ATT_VTHI + o] = h16;
        g_bf[ATT_VTLO + o] = l16;
    }
}

// ================= HMMA bf16x3 GEMM with fused epilogue =================
static constexpr int OPB  = 128 * 40 * 2;
static constexpr int STAGEB = 4 * OPB;
static constexpr int GSMEM = 2 * STAGEB;

__device__ __forceinline__ void cp_stage(const __nv_bfloat16* __restrict__ src, int kp,
                                         int kb, int rbase, int rlimit,
                                         uint32_t dstbase, int tid) {
#pragma unroll
    for (int rep = 0; rep < 2; rep++) {
        const int u = tid + rep * 256;
        const int r = u >> 2, seg = u & 3;
        const int gr = rbase + r;
        const int cl = (gr < rlimit) ? gr : (rlimit - 1);
        const void* gsrc = src + (size_t)cl * kp + kb + seg * 8;
        cp_async16(dstbase + r * 80 + seg * 16, gsrc, (gr < rlimit) ? 16 : 0);
    }
}

// epilogue modes: splitHi>=0 -> write bf16 hi/lo [M,1024]; ropeF!=null -> apply rope first.
__global__ __launch_bounds__(256, 1) void gemm_hmma(int coff, int splitHi, int splitLo,
                                                    const float* __restrict__ ropeF,
                                                    int M, int N, int kp, int nchunk,
                                                    int bhi, int blo) {
    extern __shared__ char smem[];
    const uint32_t sb = smem_to_u32(smem);
    const int tid = threadIdx.x;
    const int wid = tid >> 5, lane = tid & 31;
    const int warpM = wid >> 2, warpN = wid & 3;
    const int lr = lane >> 2, lc = (lane & 3) * 2;
    const int rowBase = blockIdx.y * 128, colBase = blockIdx.x * 128;

    const __nv_bfloat16* Ahi = g_bf + OFF_AHI;
    const __nv_bfloat16* Alo = g_bf + OFF_ALO;
    const __nv_bfloat16* Bhi = g_bf + bhi;
    const __nv_bfloat16* Blo = g_bf + blo;

    // ldmatrix per-lane address offsets (within operand tile, excluding kk/base)
    const int j = lane >> 3, r = lane & 7;
    const uint32_t aLM = (uint32_t)((warpM * 64 + (j & 1) * 8 + r) * 80 + (j >> 1) * 16);
    const uint32_t bLM = (uint32_t)((warpN * 32 + (j >> 1) * 8 + r) * 80 + (j & 1) * 16);

    float C[4][4][4];
#pragma unroll
    for (int mt = 0; mt < 4; mt++)
#pragma unroll
        for (int nt = 0; nt < 4; nt++)
#pragma unroll
            for (int jj = 0; jj < 4; jj++) C[mt][nt][jj] = 0.f;

    cp_stage(Ahi, kp, 0, rowBase, M, sb + 0 * OPB, tid);
    cp_stage(Alo, kp, 0, rowBase, M, sb + 1 * OPB, tid);
    cp_stage(Bhi, kp, 0, colBase, N, sb + 2 * OPB, tid);
    cp_stage(Blo, kp, 0, colBase, N, sb + 3 * OPB, tid);
    CP_COMMIT();

    for (int c = 0; c < nchunk; c++) {
        if (c + 1 < nchunk) {
            const uint32_t nb = sb + ((c + 1) & 1) * STAGEB;
            const int kb = (c + 1) * 32;
            cp_stage(Ahi, kp, kb, rowBase, M, nb + 0 * OPB, tid);
            cp_stage(Alo, kp, kb, rowBase, M, nb + 1 * OPB, tid);
            cp_stage(Bhi, kp, kb, colBase, N, nb + 2 * OPB, tid);
            cp_stage(Blo, kp, kb, colBase, N, nb + 3 * OPB, tid);
            CP_COMMIT();
            CP_WAIT(1);
        } else {
            CP_WAIT(0);
        }
        __syncthreads();

        const uint32_t buf = sb + (c & 1) * STAGEB;
        const uint32_t aHiB = buf, aLoB = buf + OPB, bHiB = buf + 2 * OPB, bLoB = buf + 3 * OPB;

#pragma unroll
        for (int ks = 0; ks < 2; ks++) {
            const uint32_t kkb = (uint32_t)(ks * 32);   // kk*2 bytes
            uint32_t ahi[4][4], alo[4][4], bh[4][2], bl[4][2];
#pragma unroll
            for (int mt = 0; mt < 4; mt++) {
                const uint32_t ao = aLM + (uint32_t)(mt * 16 * 80) + kkb;
                ldmx4(ahi[mt][0], ahi[mt][1], ahi[mt][2], ahi[mt][3], aHiB + ao);
                ldmx4(alo[mt][0], alo[mt][1], alo[mt][2], alo[mt][3], aLoB + ao);
            }
#pragma unroll
            for (int p = 0; p < 2; p++) {
                const uint32_t bo = bLM + (uint32_t)(p * 16 * 80) + kkb;
                ldmx4(bh[2 * p][0], bh[2 * p][1], bh[2 * p + 1][0], bh[2 * p + 1][1], bHiB + bo);
                ldmx4(bl[2 * p][0], bl[2 * p][1], bl[2 * p + 1][0], bl[2 * p + 1][1], bLoB + bo);
            }
#pragma unroll
            for (int mt = 0; mt < 4; mt++)
#pragma unroll
                for (int nt = 0; nt < 4; nt++) {
                    mma16816(C[mt][nt], ahi[mt], bh[nt]);
                    mma16816(C[mt][nt], ahi[mt], bl[nt]);
                    mma16816(C[mt][nt], alo[mt], bh[nt]);
                }
        }
        __syncthreads();
    }

    if (splitHi >= 0) {
        // N == 1024 path: optional rope, then hi/lo split write
        __nv_bfloat16* __restrict__ GH = g_bf + splitHi;
        __nv_bfloat16* __restrict__ GL = g_bf + splitLo;
#pragma unroll
        for (int mt = 0; mt < 4; mt++) {
            const int row0 = rowBase + warpM * 64 + mt * 16 + lr;
#pragma unroll
            for (int nt = 0; nt < 4; nt++) {
                const int col = colBase + warpN * 32 + nt * 8 + lc;
                float v0 = C[mt][nt][0], v1 = C[mt][nt][1];
                float v2 = C[mt][nt][2], v3 = C[mt][nt][3];
                if (ropeF) {
                    const int i = (col & 63) >> 1;
                    const int t0 = row0 & (T_ - 1), t1 = (row0 + 8) & (T_ - 1);
                    const float c0 = ropeF[(t0 * 32 + i) * 2], s0 = ropeF[(t0 * 32 + i) * 2 + 1];
                    const float c1 = ropeF[(t1 * 32 + i) * 2], s1 = ropeF[(t1 * 32 + i) * 2 + 1];
                    const float a0 = v0 * c0 - v1 * s0, b0 = v0 * s0 + v1 * c0;
                    const float a1 = v2 * c1 - v3 * s1, b1 = v2 * s1 + v3 * c1;
                    v0 = a0; v1 = b0; v2 = a1; v3 = b1;
                }
                uint32_t hi, lo;
                pack_split2(v0, v1, hi, lo);
                *(uint32_t*)&GH[(size_t)row0 * 1024 + col] = hi;
                *(uint32_t*)&GL[(size_t)row0 * 1024 + col] = lo;
                pack_split2(v2, v3, hi, lo);
                *(uint32_t*)&GH[(size_t)(row0 + 8) * 1024 + col] = hi;
                *(uint32_t*)&GL[(size_t)(row0 + 8) * 1024 + col] = lo;
            }
        }
    } else {
        float* __restrict__ Co = g_scratch + coff;
#pragma unroll
        for (int mt = 0; mt < 4; mt++) {
            const int row0 = rowBase + warpM * 64 + mt * 16 + lr;
#pragma unroll
            for (int nt = 0; nt < 4; nt++) {
                const int col = colBase + warpN * 32 + nt * 8 + lc;
                if (col < N) {
                    *(float2*)(Co + (size_t)row0 * N + col) = make_float2(C[mt][nt][0], C[mt][nt][1]);
                    *(float2*)(Co + (size_t)(row0 + 8) * N + col) = make_float2(C[mt][nt][2], C[mt][nt][3]);
                }
            }
        }
    }
}

// ================= tensor-core flash attention (bf16x3) =================
static constexpr int FROW = 144;
static constexpr int F_QOP = 128 * FROW;
static constexpr int F_KOP = 64 * FROW;
static constexpr int F_STAGE = 4 * F_KOP;
static constexpr int FSMEM = 2 * F_QOP + 2 * F_STAGE;

template <bool CAUSAL>
__global__ __launch_bounds__(256) void flash_mma(int Tq, int Tk) {
    extern __shared__ char smem[];
    const uint32_t sb = smem_to_u32(smem);
    const uint32_t qHiB = sb, qLoB = sb + F_QOP;
    const uint32_t stg0 = sb + 2 * F_QOP;

    const int tid = threadIdx.x;
    const int wid = tid >> 5, lane = tid & 31;
    const int g = lane >> 2, t4 = lane & 3;
    const int q0 = blockIdx.x * 128;
    const int h = blockIdx.y, b = blockIdx.z;

    const __nv_bfloat16* Qhi = g_bf + ATT_QHI;
    const __nv_bfloat16* Qlo = g_bf + ATT_QLO;
    const __nv_bfloat16* Khi = g_bf + ATT_KHI;
    const __nv_bfloat16* Klo = g_bf + ATT_KLO;
    const __nv_bfloat16* Vthi = g_bf + ATT_VTHI;
    const __nv_bfloat16* Vtlo = g_bf + ATT_VTLO;

#pragma unroll
    for (int rep = 0; rep < 8; rep++) {
        const int u = tid + rep * 256;
        const int op = u >> 10;
        const int r = (u >> 3) & 127, seg = u & 7;
        const __nv_bfloat16* src = (op ? Qlo : Qhi) +
            ((size_t)(b * Tq + q0 + r)) * D_ + h * HD_ + seg * 8;
        cp_async16((op ? qLoB : qHiB) + r * FROW + seg * 16, src, 16);
    }
    {
#pragma unroll
        for (int rep = 0; rep < 8; rep++) {
            const int u = tid + rep * 256;
            const int op = u >> 9;
            const int r = (u >> 3) & 63, seg = u & 7;
            const __nv_bfloat16* src;
            if (op < 2)
                src = (op ? Klo : Khi) + ((size_t)(b * Tk + r)) * D_ + h * HD_ + seg * 8;
            else
                src = (op == 2 ? Vthi : Vtlo) +
                      ((size_t)((b * H_ + h) * HD_ + r)) * Tk + seg * 8;
            cp_async16(stg0 + op * F_KOP + r * FROW + seg * 16, src, 16);
        }
    }
    CP_COMMIT();

    float o[8][4];
#pragma unroll
    for (int nd = 0; nd < 8; nd++)
#pragma unroll
        for (int jj = 0; jj < 4; jj++) o[nd][jj] = 0.f;
    float m0 = -CUDART_INF_F, m1 = -CUDART_INF_F, l0 = 0.f, l1 = 0.f;
    uint32_t aqh[4][4], aql[4][4];

    const int kend = CAUSAL ? (q0 + 128) : Tk;
    const int niter = kend / 64;

    for (int c = 0; c < niter; c++) {
        const int k0 = c * 64;
        if (c + 1 < niter) {
            const int kn = k0 + 64;
            const uint32_t nstg = stg0 + ((c + 1) & 1) * F_STAGE;
#pragma unroll
            for (int rep = 0; rep < 8; rep++) {
                const int u = tid + rep * 256;
                const int op = u >> 9;
                const int r = (u >> 3) & 63, seg = u & 7;
                const __nv_bfloat16* src;
                if (op < 2)
                    src = (op ? Klo : Khi) + ((size_t)(b * Tk + kn + r)) * D_ + h * HD_ + seg * 8;
                else
                    src = (op == 2 ? Vthi : Vtlo) +
                          ((size_t)((b * H_ + h) * HD_ + r)) * Tk + kn + seg * 8;
                cp_async16(nstg + op * F_KOP + r * FROW + seg * 16, src, 16);
            }
            CP_COMMIT();
            CP_WAIT(1);
        } else {
            CP_WAIT(0);
        }
        __syncthreads();

        if (c == 0) {
#pragma unroll
            for (int kt = 0; kt < 4; kt++) {
                const uint32_t off = (uint32_t)((16 * wid + g) * FROW + (kt * 16 + 2 * t4) * 2);
                lds32(aqh[kt][0], qHiB + off);
                lds32(aqh[kt][1], qHiB + off + 8 * FROW);
                lds32(aqh[kt][2], qHiB + off + 16);
                lds32(aqh[kt][3], qHiB + off + 8 * FROW + 16);
                lds32(aql[kt][0], qLoB + off);
                lds32(aql[kt][1], qLoB + off + 8 * FROW);
                lds32(aql[kt][2], qLoB + off + 16);
                lds32(aql[kt][3], qLoB + off + 8 * FROW + 16);
            }
        }

        const uint32_t buf = stg0 + (c & 1) * F_STAGE;
        const uint32_t kHiB = buf, kLoB = buf + F_KOP;
        const uint32_t vHiB = buf + 2 * F_KOP, vLoB = buf + 3 * F_KOP;

        float s[8][4];
#pragma unroll
        for (int nt = 0; nt < 8; nt++) {
#pragma unroll
            for (int jj = 0; jj < 4; jj++) s[nt][jj] = 0.f;
#pragma unroll
            for (int kt = 0; kt < 4; kt++) {
                const uint32_t off = (uint32_t)((nt * 8 + g) * FROW + (kt * 16 + 2 * t4) * 2);
                uint32_t bh[2], bl[2];
                lds32(bh[0], kHiB + off); lds32(bh[1], kHiB + off + 16);
                lds32(bl[0], kLoB + off); lds32(bl[1], kLoB + off + 16);
                mma16816(s[nt], aqh[kt], bh);
                mma16816(s[nt], aqh[kt], bl);
                mma16816(s[nt], aql[kt], bh);
            }
        }

        const int row0 = q0 + 16 * wid + g, row1 = row0 + 8;
        const bool domask = CAUSAL && (k0 + 63 > q0);
#pragma unroll
        for (int nt = 0; nt < 8; nt++) {
            const int col = k0 + nt * 8 + 2 * t4;
#pragma unroll
            for (int jj = 0; jj < 4; jj++) s[nt][jj] *= 0.125f;
            if (domask) {
                if (col > row0)     s[nt][0] = -1e30f;
                if (col + 1 > row0) s[nt][1] = -1e30f;
                if (col > row1)     s[nt][2] = -1e30f;
                if (col + 1 > row1) s[nt][3] = -1e30f;
            }
        }

        float mx0 = -CUDART_INF_F, mx1 = -CUDART_INF_F;
#pragma unroll
        for (int nt = 0; nt < 8; nt++) {
            mx0 = fmaxf(mx0, fmaxf(s[nt][0], s[nt][1]));
            mx1 = fmaxf(mx1, fmaxf(s[nt][2], s[nt][3]));
        }
        mx0 = fmaxf(mx0, __shfl_xor_sync(0xffffffffu, mx0, 1));
        mx0 = fmaxf(mx0, __shfl_xor_sync(0xffffffffu, mx0, 2));
        mx1 = fmaxf(mx1, __shfl_xor_sync(0xffffffffu, mx1, 1));
        mx1 = fmaxf(mx1, __shfl_xor_sync(0xffffffffu, mx1, 2));
        const float mn0 = fmaxf(m0, mx0), mn1 = fmaxf(m1, mx1);
        const float sc0 = __expf(m0 - mn0), sc1 = __expf(m1 - mn1);

        uint32_t ph[8][2], pl[8][2];
        float sum0 = 0.f, sum1 = 0.f;
#pragma unroll
        for (int nt = 0; nt < 8; nt++) {
            const float p0 = __expf(s[nt][0] - mn0);
            const float p1 = __expf(s[nt][1] - mn0);
            const float p2 = __expf(s[nt][2] - mn1);
            const float p3 = __expf(s[nt][3] - mn1);
            sum0 += p0 + p1; sum1 += p2 + p3;
            pack_split2(p0, p1, ph[nt][0], pl[nt][0]);
            pack_split2(p2, p3, ph[nt][1], pl[nt][1]);
        }
        sum0 += __shfl_xor_sync(0xffffffffu, sum0, 1);
        sum0 += __shfl_xor_sync(0xffffffffu, sum0, 2);
        sum1 += __shfl_xor_sync(0xffffffffu, sum1, 1);
        sum1 += __shfl_xor_sync(0xffffffffu, sum1, 2);
        l0 = l0 * sc0 + sum0; l1 = l1 * sc1 + sum1;
        m0 = mn0; m1 = mn1;

#pragma unroll
        for (int nd = 0; nd < 8; nd++) {
            o[nd][0] *= sc0; o[nd][1] *= sc0;
            o[nd][2] *= sc1; o[nd][3] *= sc1;
        }

#pragma unroll
        for (int jj = 0; jj < 4; jj++) {
            const uint32_t ah[4] = {ph[2 * jj][0], ph[2 * jj][1], ph[2 * jj + 1][0], ph[2 * jj + 1][1]};
            const uint32_t al[4] = {pl[2 * jj][0], pl[2 * jj][1], pl[2 * jj + 1][0], pl[2 * jj + 1][1]};
#pragma unroll
            for (int nd = 0; nd < 8; nd++) {
                const uint32_t off = (uint32_t)((nd * 8 + g) * FROW + (jj * 16 + 2 * t4) * 2);
                uint32_t bh[2], bl[2];
                lds32(bh[0], vHiB + off); lds32(bh[1], vHiB + off + 16);
                lds32(bl[0], vLoB + off); lds32(bl[1], vLoB + off + 16);
                mma16816(o[nd], ah, bh);
                mma16816(o[nd], ah, bl);
                mma16816(o[nd], al, bh);
            }
        }
        __syncthreads();
    }

    // epilogue: split-write directly into GEMM act slots [row, 1024]
    const float inv0 = 1.f / l0, inv1 = 1.f / l1;
    __nv_bfloat16* __restrict__ GH = g_bf + OFF_AHI;
    __nv_bfloat16* __restrict__ GL = g_bf + OFF_ALO;
    const int row0 = q0 + 16 * wid + g;
#pragma unroll
    for (int nd = 0; nd < 8; nd++) {
        const int col = h * HD_ + nd * 8 + 2 * t4;
        uint32_t hi, lo;
        pack_split2(o[nd][0] * inv0, o[nd][1] * inv0, hi, lo);
        *(uint32_t*)&GH[(size_t)(b * Tq + row0) * 1024 + col] = hi;
        *(uint32_t*)&GL[(size_t)(b * Tq + row0) * 1024 + col] = lo;
        pack_split2(o[nd][2] * inv1, o[nd][3] * inv1, hi, lo);
        *(uint32_t*)&GH[(size_t)(b * Tq + row0 + 8) * 1024 + col] = hi;
        *(uint32_t*)&GL[(size_t)(b * Tq + row0 + 8) * 1024 + col] = lo;
    }
}

// ================= residual + RMSNorm (+ optional split write) =================
__global__ __launch_bounds__(256) void residual_rmsnorm(const float* __restrict__ xext, int xoff,
                                                        int doff,
                                                        const float* __restrict__ g,
                                                        float* __restrict__ outext, int outoff,
                                                        int splitHi, int splitLo) {
    const float* __restrict__ xin = xext ? xext : (const float*)(g_scratch + xoff);
    const float* __restrict__ d = g_scratch + doff;
    float* __restrict__ out = outext ? outext : (g_scratch + outoff);

    __shared__ float red[8];
    const int row = blockIdx.x, tid = threadIdx.x;
    const size_t base = (size_t)row * D_;
    float4 a = *(const float4*)(xin + base + tid * 4);
    float4 bb = *(const float4*)(d + base + tid * 4);
    const float v0 = a.x + bb.x, v1 = a.y + bb.y, v2 = a.z + bb.z, v3 = a.w + bb.w;
    float ss = v0 * v0 + v1 * v1 + v2 * v2 + v3 * v3;
#pragma unroll
    for (int o = 16; o > 0; o >>= 1) ss += __shfl_xor_sync(0xffffffffu, ss, o);
    if ((tid & 31) == 0) red[tid >> 5] = ss;
    __syncthreads();
    if (tid < 8) {
        float t = red[tid];
#pragma unroll
        for (int o = 4; o > 0; o >>= 1) t += __shfl_xor_sync(0xffu, t, o);
        if (tid == 0) red[0] = t;
    }
    __syncthreads();
    const float r = rsqrtf(red[0] * (1.f / (float)D_) + EPS_);
    float4 gg = *(const float4*)(g + tid * 4);
    float4 o4 = make_float4(v0 * r * gg.x, v1 * r * gg.y, v2 * r * gg.z, v3 * r * gg.w);
    *(float4*)(out + base + tid * 4) = o4;
    if (splitHi >= 0) {
        uint32_t h0, l0, h1, l1;
        pack_split2(o4.x, o4.y, h0, l0);
        pack_split2(o4.z, o4.w, h1, l1);
        uint2 H = make_uint2(h0, h1), L = make_uint2(l0, l1);
        *(uint2*)&g_bf[splitHi + base + tid * 4] = H;
        *(uint2*)&g_bf[splitLo + base + tid * 4] = L;
    }
}

// ================= SwiGLU gate -> padded split [M,2752] =================
__global__ void silu_split(int h1off, int h3off, int M) {
    const int idx = blockIdx.x * blockDim.x + threadIdx.x;   // M * 688
    const int kq = 2752 >> 2;
    if (idx >= M * kq) return;
    const int row = idx / kq;
    const int c4 = (idx - row * kq) * 4;
    uint32_t h0, l0, h1, l1;
    if (c4 < HIDDEN_) {
        const float4 a = *(const float4*)(g_scratch + h1off + (size_t)row * HIDDEN_ + c4);
        const float4 b = *(const float4*)(g_scratch + h3off + (size_t)row * HIDDEN_ + c4);
        const float y0 = a.x / (1.f + __expf(-a.x)) * b.x;
        const float y1 = a.y / (1.f + __expf(-a.y)) * b.y;
        const float y2 = a.z / (1.f + __expf(-a.z)) * b.z;
        const float y3 = a.w / (1.f + __expf(-a.w)) * b.w;
        pack_split2(y0, y1, h0, l0);
        pack_split2(y2, y3, h1, l1);
    } else {
        h0 = l0 = h1 = l1 = 0u;
    }
    const size_t o = (size_t)row * 2752 + c4;
    *(uint2*)&g_bf[OFF_AHI + o] = make_uint2(h0, h1);
    *(uint2*)&g_bf[OFF_ALO + o] = make_uint2(l0, l1);
}

// ================= launcher =================
static void launch_gemm(int coff, int splitHi, int splitLo, const float* ropeF,
                        int M, int N, int kp, int whi, int wlo) {
    gemm_hmma<<<dim3((N + 127) / 128, M / 128), 256, GSMEM>>>(
        coff, splitHi, splitLo, ropeF, M, N, kp, kp / 32, whi, wlo);
}
static void launch_conv_wt(const float* W, int K, int N, int Kp, int wi) {
    conv_wt_t<<<dim3(Kp / 32, (N + 31) / 32), dim3(32, 8)>>>(W, K, N, Kp, WHI(wi), WLO(wi));
}

extern "C" void kernel_launch(void* const* d_in, const int* in_sizes, int n_in,
                              void* d_out, int out_size) {
    const float* x     = (const float*)d_in[0];
    const float* mem   = (const float*)d_in[1];
    const float* freqs = (const float*)d_in[2];
    const float* sa_wq = (const float*)d_in[4];
    const float* sa_wk = (const float*)d_in[5];
    const float* sa_wv = (const float*)d_in[6];
    const float* sa_wo = (const float*)d_in[7];
    const float* ca_wq = (const float*)d_in[8];
    const float* ca_wk = (const float*)d_in[9];
    const float* ca_wv = (const float*)d_in[10];
    const float* ca_wo = (const float*)d_in[11];
    const float* w1    = (const float*)d_in[12];
    const float* w3    = (const float*)d_in[13];
    const float* w2    = (const float*)d_in[14];
    const float* gsa   = (const float*)d_in[15];
    const float* gca   = (const float*)d_in[16];
    const float* gffn  = (const float*)d_in[17];
    float* out = (float*)d_out;

    cudaFuncSetAttribute((const void*)gemm_hmma,
                         cudaFuncAttributeMaxDynamicSharedMemorySize, GSMEM);
    cudaFuncSetAttribute((const void*)flash_mma<true>,
                         cudaFuncAttributeMaxDynamicSharedMemorySize, FSMEM);
    cudaFuncSetAttribute((const void*)flash_mma<false>,
                         cudaFuncAttributeMaxDynamicSharedMemorySize, FSMEM);

    const int MT = B_ * T_;     // 8192
    const int MKV = B_ * TKV_;  // 2048
    const dim3 gflash(T_ / 128, H_, B_);

    // ---- self-attention ----
    conv_act<<<(MT * 256 + 255) / 256, 256>>>(x, MT, D_, D_);                  // #0
    launch_conv_wt(sa_wq, D_, D_, D_, 0);                                      // #1
    launch_conv_wt(sa_wk, D_, D_, D_, 1);                                      // #2
    launch_conv_wt(sa_wv, D_, D_, D_, 2);                                      // #3
    launch_conv_wt(sa_wo, D_, D_, D_, 3);                                      // #4
    launch_gemm(0, ATT_QHI, ATT_QLO, freqs, MT, D_, D_, WHI(0), WLO(0));       // #5 <- profiled
    launch_gemm(0, ATT_KHI, ATT_KLO, freqs, MT, D_, D_, WHI(1), WLO(1));
    launch_gemm(OFF_V, -1, -1, nullptr, MT, D_, D_, WHI(2), WLO(2));
    conv_v_t<<<dim3(T_ / 32, 2, B_ * H_), dim3(32, 8)>>>(OFF_V, T_);
    flash_mma<true><<<gflash, 256, FSMEM>>>(T_, T_);
    launch_gemm(OFF_Q, -1, -1, nullptr, MT, D_, D_, WHI(3), WLO(3));
    residual_rmsnorm<<<MT, 256>>>(x, 0, OFF_Q, gsa, nullptr, OFF_X1, OFF_AHI, OFF_ALO);

    // ---- cross-attention ----
    launch_conv_wt(ca_wq, D_, D_, D_, 4);
    launch_conv_wt(ca_wk, D_, D_, D_, 5);
    launch_conv_wt(ca_wv, D_, D_, D_, 6);
    launch_conv_wt(ca_wo, D_, D_, D_, 7);
    launch_gemm(0, ATT_QHI, ATT_QLO, nullptr, MT, D_, D_, WHI(4), WLO(4));
    conv_act<<<(MKV * 256 + 255) / 256, 256>>>(mem, MKV, D_, D_);
    launch_gemm(0, ATT_KHI, ATT_KLO, nullptr, MKV, D_, D_, WHI(5), WLO(5));
    launch_gemm(OFF_V, -1, -1, nullptr, MKV, D_, D_, WHI(6), WLO(6));
    conv_v_t<<<dim3(TKV_ / 32, 2, B_ * H_), dim3(32, 8)>>>(OFF_V, TKV_);
    flash_mma<false><<<gflash, 256, FSMEM>>>(T_, TKV_);
    launch_gemm(OFF_Q, -1, -1, nullptr, MT, D_, D_, WHI(7), WLO(7));
    residual_rmsnorm<<<MT, 256>>>(nullptr, OFF_X1, OFF_Q, gca, nullptr, OFF_X2, OFF_AHI, OFF_ALO);

    // ---- FFN ----
    launch_conv_wt(w1, D_, HIDDEN_, D_, 8);
    launch_conv_wt(w3, D_, HIDDEN_, D_, 9);
    launch_conv_wt(w2, HIDDEN_, D_, 2752, 10);
    launch_gemm(OFF_H1, -1, -1, nullptr, MT, HIDDEN_, D_, WHI(8), WLO(8));
    launch_gemm(OFF_H3B, -1, -1, nullptr, MT, HIDDEN_, D_, WHI(9), WLO(9));
    silu_split<<<(MT * 688 + 255) / 256, 256>>>(OFF_H1, OFF_H3B, MT);
    launch_gemm(OFF_FT2, -1, -1, nullptr, MT, D_, 2752, WHI(10), WLO(10));
    residual_rmsnorm<<<MT, 256>>>(nullptr, OFF_X2, OFF_FT2, gffn, out, 0, -1, -1);
}